// round 3
// baseline (speedup 1.0000x reference)
#include <cuda_runtime.h>

// Fused sum-over-seq + concat:  out[b,i,d] = sum_l x_i[b,l,d]
// 8 inputs x_i : [512, L_i, 128] fp32, L_i = 64*(i+1); out : [512, 8, 128] fp32.
//
// R3 (= R2 resubmitted after infra failure): uniform warp-chunks for perfect
// load balance.
//   - chunk = 16 rows x 128 floats (8KB read) of one (input i, batch b)
//   - one warp per chunk; lane c owns float4 column c; 16 fully-unrolled LDG.128
//   - partial sums accumulated into out via red.global.add.v4.f32 (L2-resident)
//   - out zero-initialized by captured cudaMemsetAsync
//
// chunk id layout: input i occupies q = chunk>>9 in [P[i], P[i+1]),
// P = {0,4,12,24,40,60,84,112,144} (input i contributes 4*(i+1) chunks per
// batch element). Within an input: b = chunk & 511, l0 = 16*(q - P[i]).
// -> no divisions anywhere on the hot path.

#define NUM_IN 8
#define BATCH 512
#define DVEC 32      // 128 floats = 32 float4 per row
#define CH 16        // rows per chunk
#define TOTAL_CHUNKS 73728   // 144 * 512

struct Args {
    const float4* in[NUM_IN];
    int len[NUM_IN];
};

__global__ __launch_bounds__(128, 16)
void sum_cat_chunk_kernel(Args args, float4* __restrict__ out) {
    const int lane  = threadIdx.x & 31;
    const int wid   = threadIdx.x >> 5;
    const int chunk = blockIdx.x * 4 + wid;

    const int b = chunk & (BATCH - 1);
    const int q = chunk >> 9;              // in [0, 144)

    // q -> input index i via prefix compare chain (predicated SELs in SASS)
    const int P1 = 4, P2 = 12, P3 = 24, P4 = 40, P5 = 60, P6 = 84, P7 = 112;
    int i = 0, Pi = 0;
    if (q >= P1) { i = 1; Pi = P1; }
    if (q >= P2) { i = 2; Pi = P2; }
    if (q >= P3) { i = 3; Pi = P3; }
    if (q >= P4) { i = 4; Pi = P4; }
    if (q >= P5) { i = 5; Pi = P5; }
    if (q >= P6) { i = 6; Pi = P6; }
    if (q >= P7) { i = 7; Pi = P7; }

    const int l0 = (q - Pi) * CH;
    const int L  = args.len[i];

    const float4* __restrict__ p =
        args.in[i] + ((size_t)b * (size_t)L + (size_t)l0) * DVEC + lane;

    float4 acc = make_float4(0.f, 0.f, 0.f, 0.f);
    #pragma unroll
    for (int r = 0; r < CH; ++r) {
        const float4 v = __ldcs(p + (size_t)r * DVEC);   // read-once: evict-first
        acc.x += v.x; acc.y += v.y; acc.z += v.z; acc.w += v.w;
    }

    float4* outp = out + ((size_t)b * NUM_IN + i) * DVEC + lane;
    asm volatile(
        "red.global.add.v4.f32 [%0], {%1, %2, %3, %4};"
        :: "l"(outp), "f"(acc.x), "f"(acc.y), "f"(acc.z), "f"(acc.w)
        : "memory");
}

extern "C" void kernel_launch(void* const* d_in, const int* in_sizes, int n_in,
                              void* d_out, int out_size) {
    Args args;
    for (int i = 0; i < NUM_IN; ++i) {
        args.in[i]  = (const float4*)d_in[i];
        args.len[i] = in_sizes[i] / (BATCH * 128);   // = L_i
    }
    // Zero-init output (memset node in the captured graph; RED accumulates on top).
    cudaMemsetAsync(d_out, 0, (size_t)out_size * sizeof(float), (cudaStream_t)0);
    sum_cat_chunk_kernel<<<TOTAL_CHUNKS / 4, 128, 0, (cudaStream_t)0>>>(
        args, (float4*)d_out);
}

// round 5
// speedup vs baseline: 1.1421x; 1.1421x over previous
#include <cuda_runtime.h>

// Fused sum-over-seq + concat:  out[b,i,d] = sum_l x_i[b,l,d]
// 8 inputs x_i : [512, L_i, 128] fp32, L_i = 64*(i+1); out : [512, 8, 128] fp32.
//
// R4: pair-balanced, atomic-free, single-node.
//   L_i + L_{7-i} = 576 rows for every pair -> pair input p with input 7-p.
//   One WARP per (batch b, pair p) task: sums both inputs' rows for batch b,
//   writes both output rows with plain STG.128. All 2048 warp-tasks are
//   byte-identical (288KB read each) -> perfect balance, single wave
//   (512 CTAs, ~3.5/SM), no memset, no atomics, no smem, no __syncthreads.
//   Latency hiding via deep MLP: 16 outstanding LDG.128 per thread.

#define NUM_IN 8
#define BATCH 512
#define DVEC 32      // 128 floats = 32 float4 per row
#define UNROLL 16    // rows in flight per thread (min L = 64, multiple of 16)

struct Args {
    const float4* in[NUM_IN];
    int len[NUM_IN];
};

__device__ __forceinline__ float4 sum_rows(const float4* __restrict__ base,
                                           int L, int lane) {
    const float4* __restrict__ p = base + lane;
    float4 acc = make_float4(0.f, 0.f, 0.f, 0.f);
    for (int l = 0; l < L; l += UNROLL) {
        float4 v[UNROLL];
        #pragma unroll
        for (int u = 0; u < UNROLL; ++u)
            v[u] = __ldcs(p + (size_t)(l + u) * DVEC);   // read-once: evict-first
        #pragma unroll
        for (int u = 0; u < UNROLL; ++u) {
            acc.x += v[u].x; acc.y += v[u].y;
            acc.z += v[u].z; acc.w += v[u].w;
        }
    }
    return acc;
}

__global__ __launch_bounds__(128, 4)
void sum_cat_pair_kernel(Args args, float4* __restrict__ out) {
    const int lane = threadIdx.x & 31;
    const int wid  = threadIdx.x >> 5;
    const int W    = blockIdx.x * 4 + wid;   // global warp-task id in [0, 2048)

    const int p = W >> 9;           // pair index 0..3
    const int b = W & (BATCH - 1);  // batch element

    const int iA = p;               // shorter input of the pair
    const int iB = (NUM_IN - 1) - p;

    const int LA = args.len[iA];
    const int LB = args.len[iB];

    const float4* baseA = args.in[iA] + (size_t)b * (size_t)LA * DVEC;
    const float4* baseB = args.in[iB] + (size_t)b * (size_t)LB * DVEC;

    const float4 accA = sum_rows(baseA, LA, lane);
    const float4 accB = sum_rows(baseB, LB, lane);

    // out[b, i, :] -> float4 index (b*8 + i)*32 + lane
    out[((size_t)b * NUM_IN + iA) * DVEC + lane] = accA;
    out[((size_t)b * NUM_IN + iB) * DVEC + lane] = accB;
}

extern "C" void kernel_launch(void* const* d_in, const int* in_sizes, int n_in,
                              void* d_out, int out_size) {
    Args args;
    for (int i = 0; i < NUM_IN; ++i) {
        args.in[i]  = (const float4*)d_in[i];
        args.len[i] = in_sizes[i] / (BATCH * 128);   // = L_i
    }
    // 2048 warp-tasks -> 512 CTAs of 4 warps, single wave on 148 SMs.
    sum_cat_pair_kernel<<<(NUM_IN / 2) * BATCH / 4, 128>>>(args, (float4*)d_out);
}